// round 10
// baseline (speedup 1.0000x reference)
#include <cuda_runtime.h>
#include <cuda_fp16.h>
#include <math.h>

#define N_ATOMS 50000
#define N_EDGES 800000
#define H_DIM   64
#define G_DIM   50
#define L_LAYERS 6
#define B_GRAPHS 128
#define T_TAB   4096
#define D_MAX   8.660254f
#define COEFF   (-12.0049988f)   // -0.5/(10/49)^2

// ---------------- scratch (device globals; no allocation) ----------------
__device__ __align__(16) float  g_h  [N_ATOMS * H_DIM];
__device__ __align__(16) __half g_hjh[N_ATOMS * H_DIM];             // fp16 hj
__device__ __align__(16) float  g_agg[N_ATOMS * H_DIM];
__device__ __align__(16) __half g_tabh[L_LAYERS * T_TAB * H_DIM];   // fp16 filter table
__device__            int    g_eidx[N_EDGES];
__device__ __align__(16) float2 g_a01[N_EDGES];
__device__ __align__(16) float  g_pool[B_GRAPHS * H_DIM + B_GRAPHS];

// ---------------- helpers ----------------
__device__ __forceinline__ void red_add4(float* p, float4 v) {
    asm volatile("red.global.add.v4.f32 [%0], {%1,%2,%3,%4};"
                 :: "l"(p), "f"(v.x), "f"(v.y), "f"(v.z), "f"(v.w) : "memory");
}
__device__ __forceinline__ void red_add1(float* p, float v) {
    asm volatile("red.global.add.f32 [%0], %1;" :: "l"(p), "f"(v) : "memory");
}

// ---------------- embedding + zero pool ----------------
__global__ void k_embed(const int* __restrict__ z, const float* __restrict__ embed) {
    int gid = blockIdx.x * 256 + threadIdx.x;
    if (gid < B_GRAPHS * H_DIM + B_GRAPHS) g_pool[gid] = 0.0f;
    if (gid >= N_ATOMS * 16) return;
    int n = gid >> 4, j = gid & 15;
    ((float4*)g_h)[gid] = ((const float4*)embed)[z[n] * 16 + j];
}

// ---------------- edge prep ----------------
__global__ void k_edge(const int* __restrict__ ei, const float* __restrict__ pos) {
    int e = blockIdx.x * 256 + threadIdx.x;
    if (e >= N_EDGES) return;
    int s = ei[e], d_ = ei[N_EDGES + e];
    float dx = pos[s*3+0] - pos[d_*3+0];
    float dy = pos[s*3+1] - pos[d_*3+1];
    float dz = pos[s*3+2] - pos[d_*3+2];
    float d  = sqrtf(dx*dx + dy*dy + dz*dz);
    float cut = (d < 10.0f) ? 0.5f * (cosf(d * 0.31415926535f) + 1.0f) : 0.0f;
    float x = d * ((float)(T_TAB - 1) / D_MAX);
    int   i = (int)x;
    if (i > T_TAB - 2) i = T_TAB - 2;
    if (i < 0) i = 0;
    float f = x - (float)i;
    g_eidx[e] = i;
    g_a01[e]  = make_float2((1.0f - f) * cut, f * cut);
}

// ---------------- filter table build (fp32 math, fp16 store) ----------------
__global__ void k_table(const float* __restrict__ w1, const float* __restrict__ b1,
                        const float* __restrict__ w2, const float* __restrict__ b2) {
    int l  = blockIdx.x >> 6;        // T_TAB/64 = 64 tiles per layer
    int tb = blockIdx.x & 63;
    int f  = threadIdx.x;            // 0..63
    __shared__ float w1s[G_DIM * 64];
    __shared__ float w2s[64 * 64];
    __shared__ float ga[G_DIM];
    __shared__ float ys[64];
    for (int i = f; i < G_DIM * 64; i += 64) w1s[i] = w1[l * G_DIM * 64 + i];
    for (int i = f; i < 64 * 64;   i += 64) w2s[i] = w2[l * 64 * 64 + i];
    float myb1 = b1[l * 64 + f];
    float myb2 = b2[l * 64 + f];
    __syncthreads();
    for (int tt = 0; tt < 64; ++tt) {
        int t = tb * 64 + tt;
        float d = (float)t * (D_MAX / (float)(T_TAB - 1));
        if (f < G_DIM) {
            float u = d - (float)f * (10.0f / 49.0f);
            ga[f] = expf(COEFF * u * u);
        }
        __syncthreads();
        float s = myb1;
        #pragma unroll
        for (int g = 0; g < G_DIM; ++g) s += ga[g] * w1s[g * 64 + f];
        ys[f] = tanhf(s);
        __syncthreads();
        float s2 = myb2;
        #pragma unroll
        for (int j = 0; j < 64; ++j) s2 += ys[j] * w2s[j * 64 + f];
        g_tabh[(l * T_TAB + t) * 64 + f] = __float2half_rn(s2);
        __syncthreads();
    }
}

// ---------------- GEMM inner: acc[4][4] += 4 x-rows * 16 W-cols ----------------
__device__ __forceinline__ void gemm_accum4(const float4* __restrict__ Ws, int cg,
                                            const float4 xv[4], int k4,
                                            float4 acc[4][4]) {
    #pragma unroll
    for (int kk = 0; kk < 4; ++kk) {
        int k = k4 * 4 + kk;
        float4 w0 = Ws[k * 16 + cg * 4 + 0];
        float4 w1 = Ws[k * 16 + cg * 4 + 1];
        float4 w2 = Ws[k * 16 + cg * 4 + 2];
        float4 w3 = Ws[k * 16 + cg * 4 + 3];
        #pragma unroll
        for (int rr = 0; rr < 4; ++rr) {
            float x = (kk == 0) ? xv[rr].x : (kk == 1) ? xv[rr].y : (kk == 2) ? xv[rr].z : xv[rr].w;
            acc[rr][0].x += x * w0.x; acc[rr][0].y += x * w0.y; acc[rr][0].z += x * w0.z; acc[rr][0].w += x * w0.w;
            acc[rr][1].x += x * w1.x; acc[rr][1].y += x * w1.y; acc[rr][1].z += x * w1.z; acc[rr][1].w += x * w1.w;
            acc[rr][2].x += x * w2.x; acc[rr][2].y += x * w2.y; acc[rr][2].z += x * w2.z; acc[rr][2].w += x * w2.w;
            acc[rr][3].x += x * w3.x; acc[rr][3].y += x * w3.y; acc[rr][3].z += x * w3.z; acc[rr][3].w += x * w3.w;
        }
    }
}

// stage a 64-row x 64-col tile of X into smem (coalesced) — 1024 float4
__device__ __forceinline__ void stage_x64(const float4* __restrict__ X4, int r0,
                                          float4* __restrict__ Xs, int tid) {
    #pragma unroll
    for (int i = 0; i < 16; ++i) {
        int idx = tid + i * 64;                  // 0..1023
        int r = r0 + (idx >> 4);
        Xs[idx] = (r < N_ATOMS) ? X4[r * 16 + (idx & 15)]
                                : make_float4(0.f, 0.f, 0.f, 0.f);
    }
}

// write 16 cols of one hj row as fp16 (2 uint4 = 16 halves)
__device__ __forceinline__ void store_hj16(int r, int cg, const float4* accrow) {
    __half2 hbuf[8];
    #pragma unroll
    for (int j = 0; j < 4; ++j) {
        hbuf[j*2+0] = __float22half2_rn(make_float2(accrow[j].x, accrow[j].y));
        hbuf[j*2+1] = __float22half2_rn(make_float2(accrow[j].z, accrow[j].w));
    }
    uint4* dst = (uint4*)(g_hjh + (size_t)r * 64 + cg * 16);
    dst[0] = *(uint4*)&hbuf[0];
    dst[1] = *(uint4*)&hbuf[4];
}

// ---------------- fused: h = h + agg@Wout + b ; hj = h_new@Wlin ; agg = 0 ----------------
// 64 threads, 64 rows per block (4 rows x 16 cols per thread).
__global__ __launch_bounds__(64) void k_fused(const float* __restrict__ Wout,
                                              const float* __restrict__ bout,
                                              const float* __restrict__ Wlin,
                                              int do2) {
    __shared__ float4 Ws[1024];     // 16 KB
    __shared__ float4 Hs[1024];     // 64 rows x 16 float4 = 16 KB
    int tid = threadIdx.x;
    int cg  = tid & 3;
    int rl0 = (tid >> 2) * 4;       // 0..60
    int r0  = blockIdx.x * 64;
    const float4* W4 = (const float4*)Wout;
    for (int i = tid; i < 1024; i += 64) Ws[i] = W4[i];
    stage_x64((const float4*)g_agg, r0, Hs, tid);
    __syncthreads();

    float4 acc[4][4];
    #pragma unroll
    for (int rr = 0; rr < 4; ++rr)
        #pragma unroll
        for (int j = 0; j < 4; ++j) acc[rr][j] = make_float4(0.f, 0.f, 0.f, 0.f);

    #pragma unroll 4
    for (int k4 = 0; k4 < 16; ++k4) {
        float4 xv[4];
        #pragma unroll
        for (int rr = 0; rr < 4; ++rr) xv[rr] = Hs[(rl0 + rr) * 16 + k4];
        gemm_accum4(Ws, cg, xv, k4, acc);
    }
    __syncthreads();                 // done reading X stage before overwrite

    const float4* B4 = (const float4*)bout;
    float4* H4  = (float4*)g_h;
    float4* Ag4 = (float4*)g_agg;
    #pragma unroll
    for (int rr = 0; rr < 4; ++rr) {
        int r = r0 + rl0 + rr;
        if (r >= N_ATOMS) continue;
        #pragma unroll
        for (int j = 0; j < 4; ++j) {
            float4 v  = acc[rr][j];
            float4 bv = B4[cg * 4 + j];
            float4 hv = H4[r * 16 + cg * 4 + j];
            v.x += bv.x + hv.x; v.y += bv.y + hv.y;
            v.z += bv.z + hv.z; v.w += bv.w + hv.w;
            H4[r * 16 + cg * 4 + j] = v;
            Hs[(rl0 + rr) * 16 + cg * 4 + j] = v;
            if (do2) Ag4[r * 16 + cg * 4 + j] = make_float4(0.f, 0.f, 0.f, 0.f);
        }
    }
    if (!do2) return;

    __syncthreads();
    const float4* W42 = (const float4*)Wlin;
    for (int i = tid; i < 1024; i += 64) Ws[i] = W42[i];
    __syncthreads();

    #pragma unroll
    for (int rr = 0; rr < 4; ++rr)
        #pragma unroll
        for (int j = 0; j < 4; ++j) acc[rr][j] = make_float4(0.f, 0.f, 0.f, 0.f);

    #pragma unroll 4
    for (int k4 = 0; k4 < 16; ++k4) {
        float4 xv[4];
        #pragma unroll
        for (int rr = 0; rr < 4; ++rr) xv[rr] = Hs[(rl0 + rr) * 16 + k4];
        gemm_accum4(Ws, cg, xv, k4, acc);
    }

    #pragma unroll
    for (int rr = 0; rr < 4; ++rr) {
        int r = r0 + rl0 + rr;
        if (r >= N_ATOMS) continue;
        store_hj16(r, cg, acc[rr]);
    }
}

// ---------------- first hj: hj = h@Wlin0 ; agg = 0 ----------------
__global__ __launch_bounds__(64) void k_hj0(const float* __restrict__ W) {
    __shared__ float4 Ws[1024];
    __shared__ float4 Xs[1024];
    int tid = threadIdx.x;
    int cg  = tid & 3;
    int rl0 = (tid >> 2) * 4;
    int r0  = blockIdx.x * 64;
    const float4* W4 = (const float4*)W;
    for (int i = tid; i < 1024; i += 64) Ws[i] = W4[i];
    stage_x64((const float4*)g_h, r0, Xs, tid);
    __syncthreads();

    float4 acc[4][4];
    #pragma unroll
    for (int rr = 0; rr < 4; ++rr)
        #pragma unroll
        for (int j = 0; j < 4; ++j) acc[rr][j] = make_float4(0.f, 0.f, 0.f, 0.f);

    #pragma unroll 4
    for (int k4 = 0; k4 < 16; ++k4) {
        float4 xv[4];
        #pragma unroll
        for (int rr = 0; rr < 4; ++rr) xv[rr] = Xs[(rl0 + rr) * 16 + k4];
        gemm_accum4(Ws, cg, xv, k4, acc);
    }

    float4* Ag4 = (float4*)g_agg;
    #pragma unroll
    for (int rr = 0; rr < 4; ++rr) {
        int r = r0 + rl0 + rr;
        if (r >= N_ATOMS) continue;
        store_hj16(r, cg, acc[rr]);
        #pragma unroll
        for (int j = 0; j < 4; ++j)
            Ag4[r * 16 + cg * 4 + j] = make_float4(0.f, 0.f, 0.f, 0.f);
    }
}

// ---------------- messages: agg[dst] += hj[src] * (a0*T[i] + a1*T[i+1]), all fp16 reads ----------------
// 16 threads per edge, 4 channels each.
__global__ __launch_bounds__(256) void k_msg(const int* __restrict__ ei, int l) {
    int gid = blockIdx.x * 256 + threadIdx.x;
    if (gid >= N_EDGES * 16) return;
    int e = gid >> 4, j = gid & 15;
    int s  = ei[e];
    int dd = ei[N_EDGES + e];
    int i  = g_eidx[e];
    float2 a = g_a01[e];
    const __half* tabh = g_tabh + (size_t)l * T_TAB * H_DIM;
    // hj: 4 halves = 8 bytes (uint2)
    uint2 hraw = *(const uint2*)(g_hjh + (size_t)s * 64 + j * 4);
    float2 ha = __half22float2(*(const __half2*)&hraw.x);
    float2 hb = __half22float2(*(const __half2*)&hraw.y);
    float2 r0 = ((const float2*)(tabh + (size_t)i * 64))[j];
    float2 r1 = ((const float2*)(tabh + (size_t)i * 64 + 64))[j];
    float2 t0a = __half22float2(*(const __half2*)&r0.x);
    float2 t0b = __half22float2(*(const __half2*)&r0.y);
    float2 t1a = __half22float2(*(const __half2*)&r1.x);
    float2 t1b = __half22float2(*(const __half2*)&r1.y);
    float4 m;
    m.x = ha.x * (a.x * t0a.x + a.y * t1a.x);
    m.y = ha.y * (a.x * t0a.y + a.y * t1a.y);
    m.z = hb.x * (a.x * t0b.x + a.y * t1b.x);
    m.w = hb.y * (a.x * t0b.y + a.y * t1b.y);
    red_add4(&g_agg[dd * 64 + j * 4], m);
}

// ---------------- pooling ----------------
__global__ void k_pool(const int* __restrict__ batch) {
    int gid = blockIdx.x * 256 + threadIdx.x;
    if (gid >= N_ATOMS * 16) return;
    int n = gid >> 4, j = gid & 15;
    int b = batch[n];
    float4 v = ((const float4*)g_h)[n * 16 + j];
    red_add4(&g_pool[b * 64 + j * 4], v);
    if (j == 0) red_add1(&g_pool[B_GRAPHS * 64 + b], 1.0f);
}

// ---------------- final MLP ----------------
__global__ void k_final(const float* __restrict__ fc1w, const float* __restrict__ fc1b,
                        const float* __restrict__ fc2w, const float* __restrict__ fc2b,
                        float* __restrict__ out) {
    int g = blockIdx.x;
    int j = threadIdx.x;
    float cnt = fmaxf(g_pool[B_GRAPHS * 64 + g], 1.0f);
    float inv = 1.0f / cnt;
    float hid = fc1b[j];
    #pragma unroll
    for (int k = 0; k < 64; ++k)
        hid += (g_pool[g * 64 + k] * inv) * fc1w[k * 32 + j];
    hid = fmaxf(hid, 0.0f);
    float p = hid * fc2w[j];
    #pragma unroll
    for (int o = 16; o > 0; o >>= 1) p += __shfl_down_sync(0xffffffffu, p, o);
    if (j == 0) out[g] = p + fc2b[0];
}

// ---------------- launch ----------------
extern "C" void kernel_launch(void* const* d_in, const int* in_sizes, int n_in,
                              void* d_out, int out_size) {
    const int*   z     = (const int*)d_in[0];
    const float* pos   = (const float*)d_in[1];
    const int*   batch = (const int*)d_in[2];
    const int*   ei    = (const int*)d_in[3];
    const float* embed = (const float*)d_in[4];
    const float* w1    = (const float*)d_in[5];
    const float* b1    = (const float*)d_in[6];
    const float* w2    = (const float*)d_in[7];
    const float* b2    = (const float*)d_in[8];
    const float* linw  = (const float*)d_in[9];
    const float* loutw = (const float*)d_in[10];
    const float* loutb = (const float*)d_in[11];
    const float* fc1w  = (const float*)d_in[12];
    const float* fc1b  = (const float*)d_in[13];
    const float* fc2w  = (const float*)d_in[14];
    const float* fc2b  = (const float*)d_in[15];
    float* out = (float*)d_out;

    const int GB = (N_ATOMS + 63) / 64;     // 782 blocks x 64 threads

    k_embed<<<(N_ATOMS * 16 + 255) / 256, 256>>>(z, embed);
    k_edge <<<(N_EDGES + 255) / 256, 256>>>(ei, pos);
    k_table<<<L_LAYERS * (T_TAB / 64), 64>>>(w1, b1, w2, b2);

    k_hj0<<<GB, 64>>>(linw);   // hj for layer 0, agg zeroed

    for (int l = 0; l < L_LAYERS; ++l) {
        k_msg<<<(N_EDGES * 16 + 255) / 256, 256>>>(ei, l);
        int do2 = (l < L_LAYERS - 1);
        k_fused<<<GB, 64>>>(loutw + (size_t)l * 64 * 64,
                            loutb + (size_t)l * 64,
                            do2 ? (linw + (size_t)(l + 1) * 64 * 64) : linw,
                            do2);
    }

    k_pool <<<(N_ATOMS * 16 + 255) / 256, 256>>>(batch);
    k_final<<<B_GRAPHS, 32>>>(fc1w, fc1b, fc2w, fc2b, out);
}

// round 12
// speedup vs baseline: 1.5824x; 1.5824x over previous
#include <cuda_runtime.h>
#include <cuda_fp16.h>
#include <math.h>

#define N_ATOMS 50000
#define N_EDGES 800000
#define H_DIM   64
#define G_DIM   50
#define L_LAYERS 6
#define B_GRAPHS 128
#define T_TAB   4096
#define D_MAX   8.660254f
#define COEFF   (-12.0049988f)   // -0.5/(10/49)^2

// ---------------- scratch (device globals; no allocation) ----------------
__device__ __align__(16) float  g_h  [N_ATOMS * H_DIM];
__device__ __align__(16) __half g_hjh[N_ATOMS * H_DIM];             // fp16 hj
__device__ __align__(16) float  g_agg[N_ATOMS * H_DIM];
__device__ __align__(16) __half g_tabh[L_LAYERS * T_TAB * H_DIM];   // fp16 filter table
__device__            int    g_eidx[N_EDGES];
__device__ __align__(16) float2 g_a01[N_EDGES];
__device__ __align__(16) float  g_pool[B_GRAPHS * H_DIM + B_GRAPHS];

// ---------------- helpers ----------------
__device__ __forceinline__ void red_add4(float* p, float4 v) {
    asm volatile("red.global.add.v4.f32 [%0], {%1,%2,%3,%4};"
                 :: "l"(p), "f"(v.x), "f"(v.y), "f"(v.z), "f"(v.w) : "memory");
}
__device__ __forceinline__ void red_add1(float* p, float v) {
    asm volatile("red.global.add.f32 [%0], %1;" :: "l"(p), "f"(v) : "memory");
}

// ---------------- embedding + zero pool ----------------
__global__ void k_embed(const int* __restrict__ z, const float* __restrict__ embed) {
    int gid = blockIdx.x * 256 + threadIdx.x;
    if (gid < B_GRAPHS * H_DIM + B_GRAPHS) g_pool[gid] = 0.0f;
    if (gid >= N_ATOMS * 16) return;
    int n = gid >> 4, j = gid & 15;
    ((float4*)g_h)[gid] = ((const float4*)embed)[z[n] * 16 + j];
}

// ---------------- edge prep ----------------
__global__ void k_edge(const int* __restrict__ ei, const float* __restrict__ pos) {
    int e = blockIdx.x * 256 + threadIdx.x;
    if (e >= N_EDGES) return;
    int s = ei[e], d_ = ei[N_EDGES + e];
    float dx = pos[s*3+0] - pos[d_*3+0];
    float dy = pos[s*3+1] - pos[d_*3+1];
    float dz = pos[s*3+2] - pos[d_*3+2];
    float d  = sqrtf(dx*dx + dy*dy + dz*dz);
    float cut = (d < 10.0f) ? 0.5f * (cosf(d * 0.31415926535f) + 1.0f) : 0.0f;
    float x = d * ((float)(T_TAB - 1) / D_MAX);
    int   i = (int)x;
    if (i > T_TAB - 2) i = T_TAB - 2;
    if (i < 0) i = 0;
    float f = x - (float)i;
    g_eidx[e] = i;
    g_a01[e]  = make_float2((1.0f - f) * cut, f * cut);
}

// ---------------- filter table build (fp32 math, fp16 store) ----------------
__global__ void k_table(const float* __restrict__ w1, const float* __restrict__ b1,
                        const float* __restrict__ w2, const float* __restrict__ b2) {
    int l  = blockIdx.x >> 6;        // T_TAB/64 = 64 tiles per layer
    int tb = blockIdx.x & 63;
    int f  = threadIdx.x;            // 0..63
    __shared__ float w1s[G_DIM * 64];
    __shared__ float w2s[64 * 64];
    __shared__ float ga[G_DIM];
    __shared__ float ys[64];
    for (int i = f; i < G_DIM * 64; i += 64) w1s[i] = w1[l * G_DIM * 64 + i];
    for (int i = f; i < 64 * 64;   i += 64) w2s[i] = w2[l * 64 * 64 + i];
    float myb1 = b1[l * 64 + f];
    float myb2 = b2[l * 64 + f];
    __syncthreads();
    for (int tt = 0; tt < 64; ++tt) {
        int t = tb * 64 + tt;
        float d = (float)t * (D_MAX / (float)(T_TAB - 1));
        if (f < G_DIM) {
            float u = d - (float)f * (10.0f / 49.0f);
            ga[f] = expf(COEFF * u * u);
        }
        __syncthreads();
        float s = myb1;
        #pragma unroll
        for (int g = 0; g < G_DIM; ++g) s += ga[g] * w1s[g * 64 + f];
        ys[f] = tanhf(s);
        __syncthreads();
        float s2 = myb2;
        #pragma unroll
        for (int j = 0; j < 64; ++j) s2 += ys[j] * w2s[j * 64 + f];
        g_tabh[(l * T_TAB + t) * 64 + f] = __float2half_rn(s2);
        __syncthreads();
    }
}

// ---------------- GEMM inner: acc[4][4] += 4 x-rows * 16 W-cols ----------------
__device__ __forceinline__ void gemm_accum4(const float4* __restrict__ Ws, int cg,
                                            const float4 xv[4], int k4,
                                            float4 acc[4][4]) {
    #pragma unroll
    for (int kk = 0; kk < 4; ++kk) {
        int k = k4 * 4 + kk;
        float4 w0 = Ws[k * 16 + cg * 4 + 0];
        float4 w1 = Ws[k * 16 + cg * 4 + 1];
        float4 w2 = Ws[k * 16 + cg * 4 + 2];
        float4 w3 = Ws[k * 16 + cg * 4 + 3];
        #pragma unroll
        for (int rr = 0; rr < 4; ++rr) {
            float x = (kk == 0) ? xv[rr].x : (kk == 1) ? xv[rr].y : (kk == 2) ? xv[rr].z : xv[rr].w;
            acc[rr][0].x += x * w0.x; acc[rr][0].y += x * w0.y; acc[rr][0].z += x * w0.z; acc[rr][0].w += x * w0.w;
            acc[rr][1].x += x * w1.x; acc[rr][1].y += x * w1.y; acc[rr][1].z += x * w1.z; acc[rr][1].w += x * w1.w;
            acc[rr][2].x += x * w2.x; acc[rr][2].y += x * w2.y; acc[rr][2].z += x * w2.z; acc[rr][2].w += x * w2.w;
            acc[rr][3].x += x * w3.x; acc[rr][3].y += x * w3.y; acc[rr][3].z += x * w3.z; acc[rr][3].w += x * w3.w;
        }
    }
}

// stage a 128-row x 64-col tile of X into smem (coalesced) — 2048 float4
__device__ __forceinline__ void stage_x(const float4* __restrict__ X4, int r0,
                                        float4* __restrict__ Xs, int tid) {
    #pragma unroll
    for (int i = 0; i < 16; ++i) {
        int idx = tid + i * 128;                 // 0..2047
        int r = r0 + (idx >> 4);
        Xs[idx] = (r < N_ATOMS) ? X4[r * 16 + (idx & 15)]
                                : make_float4(0.f, 0.f, 0.f, 0.f);
    }
}

// write 16 cols of one hj row as fp16 (2 uint4 = 16 halves)
__device__ __forceinline__ void store_hj16(int r, int cg, const float4* accrow) {
    __half2 hbuf[8];
    #pragma unroll
    for (int j = 0; j < 4; ++j) {
        hbuf[j*2+0] = __float22half2_rn(make_float2(accrow[j].x, accrow[j].y));
        hbuf[j*2+1] = __float22half2_rn(make_float2(accrow[j].z, accrow[j].w));
    }
    uint4* dst = (uint4*)(g_hjh + (size_t)r * 64 + cg * 16);
    dst[0] = *(uint4*)&hbuf[0];
    dst[1] = *(uint4*)&hbuf[4];
}

// ---------------- fused: h = h + agg@Wout + b ; hj = h_new@Wlin ; agg = 0 ----------------
// 128 threads, 128 rows per block (4 rows x 16 cols per thread). X staged in smem.
__global__ __launch_bounds__(128) void k_fused(const float* __restrict__ Wout,
                                               const float* __restrict__ bout,
                                               const float* __restrict__ Wlin,
                                               int do2) {
    __shared__ float4 Ws[1024];     // 16 KB
    __shared__ float4 Hs[2048];     // 128 rows x 16 float4 = 32 KB (X stage, then h_new)
    int tid = threadIdx.x;
    int cg  = tid & 3;
    int rl0 = (tid >> 2) * 4;       // 0..124
    int r0  = blockIdx.x * 128;
    const float4* W4 = (const float4*)Wout;
    for (int i = tid; i < 1024; i += 128) Ws[i] = W4[i];
    stage_x((const float4*)g_agg, r0, Hs, tid);
    __syncthreads();

    float4 acc[4][4];
    #pragma unroll
    for (int rr = 0; rr < 4; ++rr)
        #pragma unroll
        for (int j = 0; j < 4; ++j) acc[rr][j] = make_float4(0.f, 0.f, 0.f, 0.f);

    #pragma unroll 4
    for (int k4 = 0; k4 < 16; ++k4) {
        float4 xv[4];
        #pragma unroll
        for (int rr = 0; rr < 4; ++rr) xv[rr] = Hs[(rl0 + rr) * 16 + k4];
        gemm_accum4(Ws, cg, xv, k4, acc);
    }
    __syncthreads();                 // done reading X stage before overwrite

    const float4* B4 = (const float4*)bout;
    float4* H4  = (float4*)g_h;
    float4* Ag4 = (float4*)g_agg;
    #pragma unroll
    for (int rr = 0; rr < 4; ++rr) {
        int r = r0 + rl0 + rr;
        if (r >= N_ATOMS) continue;
        #pragma unroll
        for (int j = 0; j < 4; ++j) {
            float4 v  = acc[rr][j];
            float4 bv = B4[cg * 4 + j];
            float4 hv = H4[r * 16 + cg * 4 + j];
            v.x += bv.x + hv.x; v.y += bv.y + hv.y;
            v.z += bv.z + hv.z; v.w += bv.w + hv.w;
            H4[r * 16 + cg * 4 + j] = v;
            Hs[(rl0 + rr) * 16 + cg * 4 + j] = v;
            if (do2) Ag4[r * 16 + cg * 4 + j] = make_float4(0.f, 0.f, 0.f, 0.f);
        }
    }
    if (!do2) return;

    __syncthreads();
    const float4* W42 = (const float4*)Wlin;
    for (int i = tid; i < 1024; i += 128) Ws[i] = W42[i];
    __syncthreads();

    #pragma unroll
    for (int rr = 0; rr < 4; ++rr)
        #pragma unroll
        for (int j = 0; j < 4; ++j) acc[rr][j] = make_float4(0.f, 0.f, 0.f, 0.f);

    #pragma unroll 4
    for (int k4 = 0; k4 < 16; ++k4) {
        float4 xv[4];
        #pragma unroll
        for (int rr = 0; rr < 4; ++rr) xv[rr] = Hs[(rl0 + rr) * 16 + k4];
        gemm_accum4(Ws, cg, xv, k4, acc);
    }

    #pragma unroll
    for (int rr = 0; rr < 4; ++rr) {
        int r = r0 + rl0 + rr;
        if (r >= N_ATOMS) continue;
        store_hj16(r, cg, acc[rr]);
    }
}

// ---------------- first hj: hj = h@Wlin0 ; agg = 0 ----------------
__global__ __launch_bounds__(128) void k_hj0(const float* __restrict__ W) {
    __shared__ float4 Ws[1024];
    __shared__ float4 Xs[2048];
    int tid = threadIdx.x;
    int cg  = tid & 3;
    int rl0 = (tid >> 2) * 4;
    int r0  = blockIdx.x * 128;
    const float4* W4 = (const float4*)W;
    for (int i = tid; i < 1024; i += 128) Ws[i] = W4[i];
    stage_x((const float4*)g_h, r0, Xs, tid);
    __syncthreads();

    float4 acc[4][4];
    #pragma unroll
    for (int rr = 0; rr < 4; ++rr)
        #pragma unroll
        for (int j = 0; j < 4; ++j) acc[rr][j] = make_float4(0.f, 0.f, 0.f, 0.f);

    #pragma unroll 4
    for (int k4 = 0; k4 < 16; ++k4) {
        float4 xv[4];
        #pragma unroll
        for (int rr = 0; rr < 4; ++rr) xv[rr] = Xs[(rl0 + rr) * 16 + k4];
        gemm_accum4(Ws, cg, xv, k4, acc);
    }

    float4* Ag4 = (float4*)g_agg;
    #pragma unroll
    for (int rr = 0; rr < 4; ++rr) {
        int r = r0 + rl0 + rr;
        if (r >= N_ATOMS) continue;
        store_hj16(r, cg, acc[rr]);
        #pragma unroll
        for (int j = 0; j < 4; ++j)
            Ag4[r * 16 + cg * 4 + j] = make_float4(0.f, 0.f, 0.f, 0.f);
    }
}

// ---------------- messages: agg[dst] += hj[src] * (a0*T[i] + a1*T[i+1]), fp16 reads ----------------
// 16 threads per edge, 4 channels each.
__global__ __launch_bounds__(256) void k_msg(const int* __restrict__ ei, int l) {
    int gid = blockIdx.x * 256 + threadIdx.x;
    if (gid >= N_EDGES * 16) return;
    int e = gid >> 4, j = gid & 15;
    int s  = ei[e];
    int dd = ei[N_EDGES + e];
    int i  = g_eidx[e];
    float2 a = g_a01[e];
    const __half* tabh = g_tabh + (size_t)l * T_TAB * H_DIM;
    // hj: 4 halves = 8 bytes (uint2)
    uint2 hraw = *(const uint2*)(g_hjh + (size_t)s * 64 + j * 4);
    float2 ha = __half22float2(*(const __half2*)&hraw.x);
    float2 hb = __half22float2(*(const __half2*)&hraw.y);
    float2 r0 = ((const float2*)(tabh + (size_t)i * 64))[j];
    float2 r1 = ((const float2*)(tabh + (size_t)i * 64 + 64))[j];
    float2 t0a = __half22float2(*(const __half2*)&r0.x);
    float2 t0b = __half22float2(*(const __half2*)&r0.y);
    float2 t1a = __half22float2(*(const __half2*)&r1.x);
    float2 t1b = __half22float2(*(const __half2*)&r1.y);
    float4 m;
    m.x = ha.x * (a.x * t0a.x + a.y * t1a.x);
    m.y = ha.y * (a.x * t0a.y + a.y * t1a.y);
    m.z = hb.x * (a.x * t0b.x + a.y * t1b.x);
    m.w = hb.y * (a.x * t0b.y + a.y * t1b.y);
    red_add4(&g_agg[dd * 64 + j * 4], m);
}

// ---------------- pooling ----------------
__global__ void k_pool(const int* __restrict__ batch) {
    int gid = blockIdx.x * 256 + threadIdx.x;
    if (gid >= N_ATOMS * 16) return;
    int n = gid >> 4, j = gid & 15;
    int b = batch[n];
    float4 v = ((const float4*)g_h)[n * 16 + j];
    red_add4(&g_pool[b * 64 + j * 4], v);
    if (j == 0) red_add1(&g_pool[B_GRAPHS * 64 + b], 1.0f);
}

// ---------------- final MLP ----------------
__global__ void k_final(const float* __restrict__ fc1w, const float* __restrict__ fc1b,
                        const float* __restrict__ fc2w, const float* __restrict__ fc2b,
                        float* __restrict__ out) {
    int g = blockIdx.x;
    int j = threadIdx.x;
    float cnt = fmaxf(g_pool[B_GRAPHS * 64 + g], 1.0f);
    float inv = 1.0f / cnt;
    float hid = fc1b[j];
    #pragma unroll
    for (int k = 0; k < 64; ++k)
        hid += (g_pool[g * 64 + k] * inv) * fc1w[k * 32 + j];
    hid = fmaxf(hid, 0.0f);
    float p = hid * fc2w[j];
    #pragma unroll
    for (int o = 16; o > 0; o >>= 1) p += __shfl_down_sync(0xffffffffu, p, o);
    if (j == 0) out[g] = p + fc2b[0];
}

// ---------------- launch ----------------
extern "C" void kernel_launch(void* const* d_in, const int* in_sizes, int n_in,
                              void* d_out, int out_size) {
    const int*   z     = (const int*)d_in[0];
    const float* pos   = (const float*)d_in[1];
    const int*   batch = (const int*)d_in[2];
    const int*   ei    = (const int*)d_in[3];
    const float* embed = (const float*)d_in[4];
    const float* w1    = (const float*)d_in[5];
    const float* b1    = (const float*)d_in[6];
    const float* w2    = (const float*)d_in[7];
    const float* b2    = (const float*)d_in[8];
    const float* linw  = (const float*)d_in[9];
    const float* loutw = (const float*)d_in[10];
    const float* loutb = (const float*)d_in[11];
    const float* fc1w  = (const float*)d_in[12];
    const float* fc1b  = (const float*)d_in[13];
    const float* fc2w  = (const float*)d_in[14];
    const float* fc2b  = (const float*)d_in[15];
    float* out = (float*)d_out;

    const int GB = (N_ATOMS + 127) / 128;   // 391 blocks x 128 threads

    k_embed<<<(N_ATOMS * 16 + 255) / 256, 256>>>(z, embed);
    k_edge <<<(N_EDGES + 255) / 256, 256>>>(ei, pos);
    k_table<<<L_LAYERS * (T_TAB / 64), 64>>>(w1, b1, w2, b2);

    k_hj0<<<GB, 128>>>(linw);   // hj for layer 0, agg zeroed

    for (int l = 0; l < L_LAYERS; ++l) {
        k_msg<<<(N_EDGES * 16 + 255) / 256, 256>>>(ei, l);
        int do2 = (l < L_LAYERS - 1);
        k_fused<<<GB, 128>>>(loutw + (size_t)l * 64 * 64,
                             loutb + (size_t)l * 64,
                             do2 ? (linw + (size_t)(l + 1) * 64 * 64) : linw,
                             do2);
    }

    k_pool <<<(N_ATOMS * 16 + 255) / 256, 256>>>(batch);
    k_final<<<B_GRAPHS, 32>>>(fc1w, fc1b, fc2w, fc2b, out);
}

// round 13
// speedup vs baseline: 1.6274x; 1.0285x over previous
#include <cuda_runtime.h>
#include <cuda_fp16.h>
#include <math.h>

#define N_ATOMS 50000
#define N_EDGES 800000
#define H_DIM   64
#define G_DIM   50
#define L_LAYERS 6
#define B_GRAPHS 128
#define T_TAB   4096
#define D_MAX   8.660254f
#define COEFF   (-12.0049988f)   // -0.5/(10/49)^2

typedef unsigned long long u64;

// ---------------- scratch (device globals; no allocation) ----------------
__device__ __align__(16) float  g_h  [N_ATOMS * H_DIM];
__device__ __align__(16) __half g_hjh[N_ATOMS * H_DIM];             // fp16 hj
__device__ __align__(16) float  g_agg[N_ATOMS * H_DIM];
__device__ __align__(16) __half g_tabh[L_LAYERS * T_TAB * H_DIM];   // fp16 filter table
__device__            int    g_eidx[N_EDGES];
__device__ __align__(16) float2 g_a01[N_EDGES];
__device__ __align__(16) float  g_pool[B_GRAPHS * H_DIM + B_GRAPHS];

// ---------------- helpers ----------------
__device__ __forceinline__ void red_add4(float* p, float4 v) {
    asm volatile("red.global.add.v4.f32 [%0], {%1,%2,%3,%4};"
                 :: "l"(p), "f"(v.x), "f"(v.y), "f"(v.z), "f"(v.w) : "memory");
}
__device__ __forceinline__ void red_add1(float* p, float v) {
    asm volatile("red.global.add.f32 [%0], %1;" :: "l"(p), "f"(v) : "memory");
}
// packed dual-FMA: d = a*b + d (per 32-bit half)
__device__ __forceinline__ void ffma2(u64& d, u64 a, u64 b) {
    asm("fma.rn.f32x2 %0, %1, %2, %0;" : "+l"(d) : "l"(a), "l"(b));
}
__device__ __forceinline__ u64 pack2(float x) {
    u64 r;
    asm("mov.b64 %0, {%1, %1};" : "=l"(r) : "r"(__float_as_uint(x)));
    return r;
}

// ---------------- embedding + zero pool ----------------
__global__ void k_embed(const int* __restrict__ z, const float* __restrict__ embed) {
    int gid = blockIdx.x * 256 + threadIdx.x;
    if (gid < B_GRAPHS * H_DIM + B_GRAPHS) g_pool[gid] = 0.0f;
    if (gid >= N_ATOMS * 16) return;
    int n = gid >> 4, j = gid & 15;
    ((float4*)g_h)[gid] = ((const float4*)embed)[z[n] * 16 + j];
}

// ---------------- edge prep ----------------
__global__ void k_edge(const int* __restrict__ ei, const float* __restrict__ pos) {
    int e = blockIdx.x * 256 + threadIdx.x;
    if (e >= N_EDGES) return;
    int s = ei[e], d_ = ei[N_EDGES + e];
    float dx = pos[s*3+0] - pos[d_*3+0];
    float dy = pos[s*3+1] - pos[d_*3+1];
    float dz = pos[s*3+2] - pos[d_*3+2];
    float d  = sqrtf(dx*dx + dy*dy + dz*dz);
    float cut = (d < 10.0f) ? 0.5f * (cosf(d * 0.31415926535f) + 1.0f) : 0.0f;
    float x = d * ((float)(T_TAB - 1) / D_MAX);
    int   i = (int)x;
    if (i > T_TAB - 2) i = T_TAB - 2;
    if (i < 0) i = 0;
    float f = x - (float)i;
    g_eidx[e] = i;
    g_a01[e]  = make_float2((1.0f - f) * cut, f * cut);
}

// ---------------- filter table build (fp32 math, fp16 store) ----------------
__global__ void k_table(const float* __restrict__ w1, const float* __restrict__ b1,
                        const float* __restrict__ w2, const float* __restrict__ b2) {
    int l  = blockIdx.x >> 6;        // T_TAB/64 = 64 tiles per layer
    int tb = blockIdx.x & 63;
    int f  = threadIdx.x;            // 0..63
    __shared__ float w1s[G_DIM * 64];
    __shared__ float w2s[64 * 64];
    __shared__ float ga[G_DIM];
    __shared__ float ys[64];
    for (int i = f; i < G_DIM * 64; i += 64) w1s[i] = w1[l * G_DIM * 64 + i];
    for (int i = f; i < 64 * 64;   i += 64) w2s[i] = w2[l * 64 * 64 + i];
    float myb1 = b1[l * 64 + f];
    float myb2 = b2[l * 64 + f];
    __syncthreads();
    for (int tt = 0; tt < 64; ++tt) {
        int t = tb * 64 + tt;
        float d = (float)t * (D_MAX / (float)(T_TAB - 1));
        if (f < G_DIM) {
            float u = d - (float)f * (10.0f / 49.0f);
            ga[f] = expf(COEFF * u * u);
        }
        __syncthreads();
        float s = myb1;
        #pragma unroll
        for (int g = 0; g < G_DIM; ++g) s += ga[g] * w1s[g * 64 + f];
        ys[f] = tanhf(s);
        __syncthreads();
        float s2 = myb2;
        #pragma unroll
        for (int j = 0; j < 64; ++j) s2 += ys[j] * w2s[j * 64 + f];
        g_tabh[(l * T_TAB + t) * 64 + f] = __float2half_rn(s2);
        __syncthreads();
    }
}

// ---------------- GEMM inner (f32x2): acc[4][8] u64 += 4 x-rows * 16 W-cols ----------------
__device__ __forceinline__ void gemm_accum4x2(const float4* __restrict__ Ws, int cg,
                                              const float4 xv[4], int k4,
                                              u64 acc[4][8]) {
    #pragma unroll
    for (int kk = 0; kk < 4; ++kk) {
        int k = k4 * 4 + kk;
        ulonglong2 w0 = *(const ulonglong2*)&Ws[k * 16 + cg * 4 + 0];
        ulonglong2 w1 = *(const ulonglong2*)&Ws[k * 16 + cg * 4 + 1];
        ulonglong2 w2 = *(const ulonglong2*)&Ws[k * 16 + cg * 4 + 2];
        ulonglong2 w3 = *(const ulonglong2*)&Ws[k * 16 + cg * 4 + 3];
        #pragma unroll
        for (int rr = 0; rr < 4; ++rr) {
            float x = (kk == 0) ? xv[rr].x : (kk == 1) ? xv[rr].y : (kk == 2) ? xv[rr].z : xv[rr].w;
            u64 xx = pack2(x);
            ffma2(acc[rr][0], xx, w0.x); ffma2(acc[rr][1], xx, w0.y);
            ffma2(acc[rr][2], xx, w1.x); ffma2(acc[rr][3], xx, w1.y);
            ffma2(acc[rr][4], xx, w2.x); ffma2(acc[rr][5], xx, w2.y);
            ffma2(acc[rr][6], xx, w3.x); ffma2(acc[rr][7], xx, w3.y);
        }
    }
}

__device__ __forceinline__ float4 unpack_acc(const u64* a, int j) {
    float2 lo = *(const float2*)&a[2*j];
    float2 hi = *(const float2*)&a[2*j+1];
    return make_float4(lo.x, lo.y, hi.x, hi.y);
}

// stage a 128-row x 64-col tile of X into smem (coalesced) — 2048 float4
__device__ __forceinline__ void stage_x(const float4* __restrict__ X4, int r0,
                                        float4* __restrict__ Xs, int tid) {
    #pragma unroll
    for (int i = 0; i < 16; ++i) {
        int idx = tid + i * 128;                 // 0..2047
        int r = r0 + (idx >> 4);
        Xs[idx] = (r < N_ATOMS) ? X4[r * 16 + (idx & 15)]
                                : make_float4(0.f, 0.f, 0.f, 0.f);
    }
}

// write 16 cols of one hj row as fp16 (2 uint4 = 16 halves)
__device__ __forceinline__ void store_hj16(int r, int cg, const float4* accrow) {
    __half2 hbuf[8];
    #pragma unroll
    for (int j = 0; j < 4; ++j) {
        hbuf[j*2+0] = __float22half2_rn(make_float2(accrow[j].x, accrow[j].y));
        hbuf[j*2+1] = __float22half2_rn(make_float2(accrow[j].z, accrow[j].w));
    }
    uint4* dst = (uint4*)(g_hjh + (size_t)r * 64 + cg * 16);
    dst[0] = *(uint4*)&hbuf[0];
    dst[1] = *(uint4*)&hbuf[4];
}

// ---------------- fused: h = h + agg@Wout + b ; hj = h_new@Wlin ; agg = 0 ----------------
// 128 threads, 128 rows per block (4 rows x 16 cols per thread). X staged in smem.
__global__ __launch_bounds__(128) void k_fused(const float* __restrict__ Wout,
                                               const float* __restrict__ bout,
                                               const float* __restrict__ Wlin,
                                               int do2) {
    __shared__ float4 Ws[1024];     // 16 KB
    __shared__ float4 Hs[2048];     // 128 rows x 16 float4 = 32 KB (X stage, then h_new)
    int tid = threadIdx.x;
    int cg  = tid & 3;
    int rl0 = (tid >> 2) * 4;       // 0..124
    int r0  = blockIdx.x * 128;
    const float4* W4 = (const float4*)Wout;
    for (int i = tid; i < 1024; i += 128) Ws[i] = W4[i];
    stage_x((const float4*)g_agg, r0, Hs, tid);
    __syncthreads();

    u64 acc[4][8];
    #pragma unroll
    for (int rr = 0; rr < 4; ++rr)
        #pragma unroll
        for (int j = 0; j < 8; ++j) acc[rr][j] = 0ULL;

    #pragma unroll 4
    for (int k4 = 0; k4 < 16; ++k4) {
        float4 xv[4];
        #pragma unroll
        for (int rr = 0; rr < 4; ++rr) xv[rr] = Hs[(rl0 + rr) * 16 + k4];
        gemm_accum4x2(Ws, cg, xv, k4, acc);
    }
    __syncthreads();                 // done reading X stage before overwrite

    const float4* B4 = (const float4*)bout;
    float4* H4  = (float4*)g_h;
    float4* Ag4 = (float4*)g_agg;
    #pragma unroll
    for (int rr = 0; rr < 4; ++rr) {
        int r = r0 + rl0 + rr;
        if (r >= N_ATOMS) continue;
        #pragma unroll
        for (int j = 0; j < 4; ++j) {
            float4 v  = unpack_acc(acc[rr], j);
            float4 bv = B4[cg * 4 + j];
            float4 hv = H4[r * 16 + cg * 4 + j];
            v.x += bv.x + hv.x; v.y += bv.y + hv.y;
            v.z += bv.z + hv.z; v.w += bv.w + hv.w;
            H4[r * 16 + cg * 4 + j] = v;
            Hs[(rl0 + rr) * 16 + cg * 4 + j] = v;
            if (do2) Ag4[r * 16 + cg * 4 + j] = make_float4(0.f, 0.f, 0.f, 0.f);
        }
    }
    if (!do2) return;

    __syncthreads();
    const float4* W42 = (const float4*)Wlin;
    for (int i = tid; i < 1024; i += 128) Ws[i] = W42[i];
    __syncthreads();

    #pragma unroll
    for (int rr = 0; rr < 4; ++rr)
        #pragma unroll
        for (int j = 0; j < 8; ++j) acc[rr][j] = 0ULL;

    #pragma unroll 4
    for (int k4 = 0; k4 < 16; ++k4) {
        float4 xv[4];
        #pragma unroll
        for (int rr = 0; rr < 4; ++rr) xv[rr] = Hs[(rl0 + rr) * 16 + k4];
        gemm_accum4x2(Ws, cg, xv, k4, acc);
    }

    #pragma unroll
    for (int rr = 0; rr < 4; ++rr) {
        int r = r0 + rl0 + rr;
        if (r >= N_ATOMS) continue;
        float4 row[4];
        #pragma unroll
        for (int j = 0; j < 4; ++j) row[j] = unpack_acc(acc[rr], j);
        store_hj16(r, cg, row);
    }
}

// ---------------- first hj: hj = h@Wlin0 ; agg = 0 ----------------
__global__ __launch_bounds__(128) void k_hj0(const float* __restrict__ W) {
    __shared__ float4 Ws[1024];
    __shared__ float4 Xs[2048];
    int tid = threadIdx.x;
    int cg  = tid & 3;
    int rl0 = (tid >> 2) * 4;
    int r0  = blockIdx.x * 128;
    const float4* W4 = (const float4*)W;
    for (int i = tid; i < 1024; i += 128) Ws[i] = W4[i];
    stage_x((const float4*)g_h, r0, Xs, tid);
    __syncthreads();

    u64 acc[4][8];
    #pragma unroll
    for (int rr = 0; rr < 4; ++rr)
        #pragma unroll
        for (int j = 0; j < 8; ++j) acc[rr][j] = 0ULL;

    #pragma unroll 4
    for (int k4 = 0; k4 < 16; ++k4) {
        float4 xv[4];
        #pragma unroll
        for (int rr = 0; rr < 4; ++rr) xv[rr] = Xs[(rl0 + rr) * 16 + k4];
        gemm_accum4x2(Ws, cg, xv, k4, acc);
    }

    float4* Ag4 = (float4*)g_agg;
    #pragma unroll
    for (int rr = 0; rr < 4; ++rr) {
        int r = r0 + rl0 + rr;
        if (r >= N_ATOMS) continue;
        float4 row[4];
        #pragma unroll
        for (int j = 0; j < 4; ++j) row[j] = unpack_acc(acc[rr], j);
        store_hj16(r, cg, row);
        #pragma unroll
        for (int j = 0; j < 4; ++j)
            Ag4[r * 16 + cg * 4 + j] = make_float4(0.f, 0.f, 0.f, 0.f);
    }
}

// ---------------- messages: agg[dst] += hj[src] * (a0*T[i] + a1*T[i+1]), fp16 reads ----------------
// 16 threads per edge, 4 channels each.
__global__ __launch_bounds__(256) void k_msg(const int* __restrict__ ei, int l) {
    int gid = blockIdx.x * 256 + threadIdx.x;
    if (gid >= N_EDGES * 16) return;
    int e = gid >> 4, j = gid & 15;
    int s  = ei[e];
    int dd = ei[N_EDGES + e];
    int i  = g_eidx[e];
    float2 a = g_a01[e];
    const __half* tabh = g_tabh + (size_t)l * T_TAB * H_DIM;
    uint2 hraw = *(const uint2*)(g_hjh + (size_t)s * 64 + j * 4);
    float2 ha = __half22float2(*(const __half2*)&hraw.x);
    float2 hb = __half22float2(*(const __half2*)&hraw.y);
    float2 r0 = ((const float2*)(tabh + (size_t)i * 64))[j];
    float2 r1 = ((const float2*)(tabh + (size_t)i * 64 + 64))[j];
    float2 t0a = __half22float2(*(const __half2*)&r0.x);
    float2 t0b = __half22float2(*(const __half2*)&r0.y);
    float2 t1a = __half22float2(*(const __half2*)&r1.x);
    float2 t1b = __half22float2(*(const __half2*)&r1.y);
    float4 m;
    m.x = ha.x * (a.x * t0a.x + a.y * t1a.x);
    m.y = ha.y * (a.x * t0a.y + a.y * t1a.y);
    m.z = hb.x * (a.x * t0b.x + a.y * t1b.x);
    m.w = hb.y * (a.x * t0b.y + a.y * t1b.y);
    red_add4(&g_agg[dd * 64 + j * 4], m);
}

// ---------------- pooling ----------------
__global__ void k_pool(const int* __restrict__ batch) {
    int gid = blockIdx.x * 256 + threadIdx.x;
    if (gid >= N_ATOMS * 16) return;
    int n = gid >> 4, j = gid & 15;
    int b = batch[n];
    float4 v = ((const float4*)g_h)[n * 16 + j];
    red_add4(&g_pool[b * 64 + j * 4], v);
    if (j == 0) red_add1(&g_pool[B_GRAPHS * 64 + b], 1.0f);
}

// ---------------- final MLP ----------------
__global__ void k_final(const float* __restrict__ fc1w, const float* __restrict__ fc1b,
                        const float* __restrict__ fc2w, const float* __restrict__ fc2b,
                        float* __restrict__ out) {
    int g = blockIdx.x;
    int j = threadIdx.x;
    float cnt = fmaxf(g_pool[B_GRAPHS * 64 + g], 1.0f);
    float inv = 1.0f / cnt;
    float hid = fc1b[j];
    #pragma unroll
    for (int k = 0; k < 64; ++k)
        hid += (g_pool[g * 64 + k] * inv) * fc1w[k * 32 + j];
    hid = fmaxf(hid, 0.0f);
    float p = hid * fc2w[j];
    #pragma unroll
    for (int o = 16; o > 0; o >>= 1) p += __shfl_down_sync(0xffffffffu, p, o);
    if (j == 0) out[g] = p + fc2b[0];
}

// ---------------- launch ----------------
extern "C" void kernel_launch(void* const* d_in, const int* in_sizes, int n_in,
                              void* d_out, int out_size) {
    const int*   z     = (const int*)d_in[0];
    const float* pos   = (const float*)d_in[1];
    const int*   batch = (const int*)d_in[2];
    const int*   ei    = (const int*)d_in[3];
    const float* embed = (const float*)d_in[4];
    const float* w1    = (const float*)d_in[5];
    const float* b1    = (const float*)d_in[6];
    const float* w2    = (const float*)d_in[7];
    const float* b2    = (const float*)d_in[8];
    const float* linw  = (const float*)d_in[9];
    const float* loutw = (const float*)d_in[10];
    const float* loutb = (const float*)d_in[11];
    const float* fc1w  = (const float*)d_in[12];
    const float* fc1b  = (const float*)d_in[13];
    const float* fc2w  = (const float*)d_in[14];
    const float* fc2b  = (const float*)d_in[15];
    float* out = (float*)d_out;

    const int GB = (N_ATOMS + 127) / 128;   // 391 blocks x 128 threads

    k_embed<<<(N_ATOMS * 16 + 255) / 256, 256>>>(z, embed);
    k_edge <<<(N_EDGES + 255) / 256, 256>>>(ei, pos);
    k_table<<<L_LAYERS * (T_TAB / 64), 64>>>(w1, b1, w2, b2);

    k_hj0<<<GB, 128>>>(linw);   // hj for layer 0, agg zeroed

    for (int l = 0; l < L_LAYERS; ++l) {
        k_msg<<<(N_EDGES * 16 + 255) / 256, 256>>>(ei, l);
        int do2 = (l < L_LAYERS - 1);
        k_fused<<<GB, 128>>>(loutw + (size_t)l * 64 * 64,
                             loutb + (size_t)l * 64,
                             do2 ? (linw + (size_t)(l + 1) * 64 * 64) : linw,
                             do2);
    }

    k_pool <<<(N_ATOMS * 16 + 255) / 256, 256>>>(batch);
    k_final<<<B_GRAPHS, 32>>>(fc1w, fc1b, fc2w, fc2b, out);
}

// round 14
// speedup vs baseline: 1.6663x; 1.0239x over previous
#include <cuda_runtime.h>
#include <cuda_fp16.h>
#include <math.h>

#define N_ATOMS 50000
#define N_EDGES 800000
#define H_DIM   64
#define G_DIM   50
#define L_LAYERS 6
#define B_GRAPHS 128
#define T_TAB   4096
#define D_MAX   8.660254f
#define COEFF   (-12.0049988f)   // -0.5/(10/49)^2
#define XS_PITCH 17              // float4 row pitch: 272B -> conflict-free across rows

typedef unsigned long long u64;

// ---------------- scratch (device globals; no allocation) ----------------
__device__ __align__(16) float  g_h  [N_ATOMS * H_DIM];
__device__ __align__(16) __half g_hjh[N_ATOMS * H_DIM];             // fp16 hj
__device__ __align__(16) float  g_agg[N_ATOMS * H_DIM];
__device__ __align__(16) __half g_tabh[L_LAYERS * T_TAB * H_DIM];   // fp16 filter table
__device__            int    g_eidx[N_EDGES];
__device__ __align__(16) float2 g_a01[N_EDGES];
__device__ __align__(16) float  g_pool[B_GRAPHS * H_DIM + B_GRAPHS];

// ---------------- helpers ----------------
__device__ __forceinline__ void red_add4(float* p, float4 v) {
    asm volatile("red.global.add.v4.f32 [%0], {%1,%2,%3,%4};"
                 :: "l"(p), "f"(v.x), "f"(v.y), "f"(v.z), "f"(v.w) : "memory");
}
__device__ __forceinline__ void red_add1(float* p, float v) {
    asm volatile("red.global.add.f32 [%0], %1;" :: "l"(p), "f"(v) : "memory");
}
// packed dual-FMA: d = a*b + d (per 32-bit half)
__device__ __forceinline__ void ffma2(u64& d, u64 a, u64 b) {
    asm("fma.rn.f32x2 %0, %1, %2, %0;" : "+l"(d) : "l"(a), "l"(b));
}
__device__ __forceinline__ u64 pack2(float x) {
    u64 r;
    asm("mov.b64 %0, {%1, %1};" : "=l"(r) : "r"(__float_as_uint(x)));
    return r;
}

// ---------------- embedding + zero pool ----------------
__global__ void k_embed(const int* __restrict__ z, const float* __restrict__ embed) {
    int gid = blockIdx.x * 256 + threadIdx.x;
    if (gid < B_GRAPHS * H_DIM + B_GRAPHS) g_pool[gid] = 0.0f;
    if (gid >= N_ATOMS * 16) return;
    int n = gid >> 4, j = gid & 15;
    ((float4*)g_h)[gid] = ((const float4*)embed)[z[n] * 16 + j];
}

// ---------------- edge prep ----------------
__global__ void k_edge(const int* __restrict__ ei, const float* __restrict__ pos) {
    int e = blockIdx.x * 256 + threadIdx.x;
    if (e >= N_EDGES) return;
    int s = ei[e], d_ = ei[N_EDGES + e];
    float dx = pos[s*3+0] - pos[d_*3+0];
    float dy = pos[s*3+1] - pos[d_*3+1];
    float dz = pos[s*3+2] - pos[d_*3+2];
    float d  = sqrtf(dx*dx + dy*dy + dz*dz);
    float cut = (d < 10.0f) ? 0.5f * (cosf(d * 0.31415926535f) + 1.0f) : 0.0f;
    float x = d * ((float)(T_TAB - 1) / D_MAX);
    int   i = (int)x;
    if (i > T_TAB - 2) i = T_TAB - 2;
    if (i < 0) i = 0;
    float f = x - (float)i;
    g_eidx[e] = i;
    g_a01[e]  = make_float2((1.0f - f) * cut, f * cut);
}

// ---------------- filter table build (fp32 math, fp16 store) ----------------
__global__ void k_table(const float* __restrict__ w1, const float* __restrict__ b1,
                        const float* __restrict__ w2, const float* __restrict__ b2) {
    int l  = blockIdx.x >> 6;        // T_TAB/64 = 64 tiles per layer
    int tb = blockIdx.x & 63;
    int f  = threadIdx.x;            // 0..63
    __shared__ float w1s[G_DIM * 64];
    __shared__ float w2s[64 * 64];
    __shared__ float ga[G_DIM];
    __shared__ float ys[64];
    for (int i = f; i < G_DIM * 64; i += 64) w1s[i] = w1[l * G_DIM * 64 + i];
    for (int i = f; i < 64 * 64;   i += 64) w2s[i] = w2[l * 64 * 64 + i];
    float myb1 = b1[l * 64 + f];
    float myb2 = b2[l * 64 + f];
    __syncthreads();
    for (int tt = 0; tt < 64; ++tt) {
        int t = tb * 64 + tt;
        float d = (float)t * (D_MAX / (float)(T_TAB - 1));
        if (f < G_DIM) {
            float u = d - (float)f * (10.0f / 49.0f);
            ga[f] = expf(COEFF * u * u);
        }
        __syncthreads();
        float s = myb1;
        #pragma unroll
        for (int g = 0; g < G_DIM; ++g) s += ga[g] * w1s[g * 64 + f];
        ys[f] = tanhf(s);
        __syncthreads();
        float s2 = myb2;
        #pragma unroll
        for (int j = 0; j < 64; ++j) s2 += ys[j] * w2s[j * 64 + f];
        g_tabh[(l * T_TAB + t) * 64 + f] = __float2half_rn(s2);
        __syncthreads();
    }
}

// ---------------- GEMM inner (f32x2): acc[4][8] u64 += 4 x-rows * 16 W-cols ----------------
__device__ __forceinline__ void gemm_accum4x2(const float4* __restrict__ Ws, int cg,
                                              const float4 xv[4], int k4,
                                              u64 acc[4][8]) {
    #pragma unroll
    for (int kk = 0; kk < 4; ++kk) {
        int k = k4 * 4 + kk;
        ulonglong2 w0 = *(const ulonglong2*)&Ws[k * 16 + cg * 4 + 0];
        ulonglong2 w1 = *(const ulonglong2*)&Ws[k * 16 + cg * 4 + 1];
        ulonglong2 w2 = *(const ulonglong2*)&Ws[k * 16 + cg * 4 + 2];
        ulonglong2 w3 = *(const ulonglong2*)&Ws[k * 16 + cg * 4 + 3];
        #pragma unroll
        for (int rr = 0; rr < 4; ++rr) {
            float x = (kk == 0) ? xv[rr].x : (kk == 1) ? xv[rr].y : (kk == 2) ? xv[rr].z : xv[rr].w;
            u64 xx = pack2(x);
            ffma2(acc[rr][0], xx, w0.x); ffma2(acc[rr][1], xx, w0.y);
            ffma2(acc[rr][2], xx, w1.x); ffma2(acc[rr][3], xx, w1.y);
            ffma2(acc[rr][4], xx, w2.x); ffma2(acc[rr][5], xx, w2.y);
            ffma2(acc[rr][6], xx, w3.x); ffma2(acc[rr][7], xx, w3.y);
        }
    }
}

__device__ __forceinline__ float4 unpack_acc(const u64* a, int j) {
    float2 lo = *(const float2*)&a[2*j];
    float2 hi = *(const float2*)&a[2*j+1];
    return make_float4(lo.x, lo.y, hi.x, hi.y);
}

// stage a 128-row x 64-col tile of X into smem (coalesced), padded pitch
__device__ __forceinline__ void stage_x(const float4* __restrict__ X4, int r0,
                                        float4* __restrict__ Xs, int tid) {
    #pragma unroll
    for (int i = 0; i < 16; ++i) {
        int idx = tid + i * 128;                 // 0..2047
        int rl  = idx >> 4;
        int c   = idx & 15;
        int r   = r0 + rl;
        Xs[rl * XS_PITCH + c] = (r < N_ATOMS) ? X4[r * 16 + c]
                                              : make_float4(0.f, 0.f, 0.f, 0.f);
    }
}

// write 16 cols of one hj row as fp16 (2 uint4 = 16 halves)
__device__ __forceinline__ void store_hj16(int r, int cg, const float4* accrow) {
    __half2 hbuf[8];
    #pragma unroll
    for (int j = 0; j < 4; ++j) {
        hbuf[j*2+0] = __float22half2_rn(make_float2(accrow[j].x, accrow[j].y));
        hbuf[j*2+1] = __float22half2_rn(make_float2(accrow[j].z, accrow[j].w));
    }
    uint4* dst = (uint4*)(g_hjh + (size_t)r * 64 + cg * 16);
    dst[0] = *(uint4*)&hbuf[0];
    dst[1] = *(uint4*)&hbuf[4];
}

// ---------------- fused: h = h + agg@Wout + b ; hj = h_new@Wlin ; agg = 0 ----------------
// 128 threads, 128 rows per block (4 rows x 16 cols per thread). X staged, padded pitch.
__global__ __launch_bounds__(128) void k_fused(const float* __restrict__ Wout,
                                               const float* __restrict__ bout,
                                               const float* __restrict__ Wlin,
                                               int do2) {
    __shared__ float4 Ws[1024];              // 16 KB
    __shared__ float4 Hs[128 * XS_PITCH];    // 34.8 KB (X stage, then h_new)
    int tid = threadIdx.x;
    int cg  = tid & 3;
    int rl0 = (tid >> 2) * 4;       // 0..124
    int r0  = blockIdx.x * 128;
    const float4* W4 = (const float4*)Wout;
    for (int i = tid; i < 1024; i += 128) Ws[i] = W4[i];
    stage_x((const float4*)g_agg, r0, Hs, tid);
    __syncthreads();

    u64 acc[4][8];
    #pragma unroll
    for (int rr = 0; rr < 4; ++rr)
        #pragma unroll
        for (int j = 0; j < 8; ++j) acc[rr][j] = 0ULL;

    #pragma unroll 4
    for (int k4 = 0; k4 < 16; ++k4) {
        float4 xv[4];
        #pragma unroll
        for (int rr = 0; rr < 4; ++rr) xv[rr] = Hs[(rl0 + rr) * XS_PITCH + k4];
        gemm_accum4x2(Ws, cg, xv, k4, acc);
    }
    __syncthreads();                 // done reading X stage before overwrite

    const float4* B4 = (const float4*)bout;
    float4* H4  = (float4*)g_h;
    float4* Ag4 = (float4*)g_agg;
    #pragma unroll
    for (int rr = 0; rr < 4; ++rr) {
        int r = r0 + rl0 + rr;
        if (r >= N_ATOMS) continue;
        #pragma unroll
        for (int j = 0; j < 4; ++j) {
            float4 v  = unpack_acc(acc[rr], j);
            float4 bv = B4[cg * 4 + j];
            float4 hv = H4[r * 16 + cg * 4 + j];
            v.x += bv.x + hv.x; v.y += bv.y + hv.y;
            v.z += bv.z + hv.z; v.w += bv.w + hv.w;
            H4[r * 16 + cg * 4 + j] = v;
            Hs[(rl0 + rr) * XS_PITCH + cg * 4 + j] = v;
            if (do2) Ag4[r * 16 + cg * 4 + j] = make_float4(0.f, 0.f, 0.f, 0.f);
        }
    }
    if (!do2) return;

    __syncthreads();
    const float4* W42 = (const float4*)Wlin;
    for (int i = tid; i < 1024; i += 128) Ws[i] = W42[i];
    __syncthreads();

    #pragma unroll
    for (int rr = 0; rr < 4; ++rr)
        #pragma unroll
        for (int j = 0; j < 8; ++j) acc[rr][j] = 0ULL;

    #pragma unroll 4
    for (int k4 = 0; k4 < 16; ++k4) {
        float4 xv[4];
        #pragma unroll
        for (int rr = 0; rr < 4; ++rr) xv[rr] = Hs[(rl0 + rr) * XS_PITCH + k4];
        gemm_accum4x2(Ws, cg, xv, k4, acc);
    }

    #pragma unroll
    for (int rr = 0; rr < 4; ++rr) {
        int r = r0 + rl0 + rr;
        if (r >= N_ATOMS) continue;
        float4 row[4];
        #pragma unroll
        for (int j = 0; j < 4; ++j) row[j] = unpack_acc(acc[rr], j);
        store_hj16(r, cg, row);
    }
}

// ---------------- first hj: hj = h@Wlin0 ; agg = 0 ----------------
__global__ __launch_bounds__(128) void k_hj0(const float* __restrict__ W) {
    __shared__ float4 Ws[1024];
    __shared__ float4 Xs[128 * XS_PITCH];
    int tid = threadIdx.x;
    int cg  = tid & 3;
    int rl0 = (tid >> 2) * 4;
    int r0  = blockIdx.x * 128;
    const float4* W4 = (const float4*)W;
    for (int i = tid; i < 1024; i += 128) Ws[i] = W4[i];
    stage_x((const float4*)g_h, r0, Xs, tid);
    __syncthreads();

    u64 acc[4][8];
    #pragma unroll
    for (int rr = 0; rr < 4; ++rr)
        #pragma unroll
        for (int j = 0; j < 8; ++j) acc[rr][j] = 0ULL;

    #pragma unroll 4
    for (int k4 = 0; k4 < 16; ++k4) {
        float4 xv[4];
        #pragma unroll
        for (int rr = 0; rr < 4; ++rr) xv[rr] = Xs[(rl0 + rr) * XS_PITCH + k4];
        gemm_accum4x2(Ws, cg, xv, k4, acc);
    }

    float4* Ag4 = (float4*)g_agg;
    #pragma unroll
    for (int rr = 0; rr < 4; ++rr) {
        int r = r0 + rl0 + rr;
        if (r >= N_ATOMS) continue;
        float4 row[4];
        #pragma unroll
        for (int j = 0; j < 4; ++j) row[j] = unpack_acc(acc[rr], j);
        store_hj16(r, cg, row);
        #pragma unroll
        for (int j = 0; j < 4; ++j)
            Ag4[r * 16 + cg * 4 + j] = make_float4(0.f, 0.f, 0.f, 0.f);
    }
}

// ---------------- messages: agg[dst] += hj[src] * (a0*T[i] + a1*T[i+1]), fp16 reads ----------------
// 16 threads per edge, 4 channels each.
__global__ __launch_bounds__(256) void k_msg(const int* __restrict__ ei, int l) {
    int gid = blockIdx.x * 256 + threadIdx.x;
    if (gid >= N_EDGES * 16) return;
    int e = gid >> 4, j = gid & 15;
    int s  = ei[e];
    int dd = ei[N_EDGES + e];
    int i  = g_eidx[e];
    float2 a = g_a01[e];
    const __half* tabh = g_tabh + (size_t)l * T_TAB * H_DIM;
    uint2 hraw = *(const uint2*)(g_hjh + (size_t)s * 64 + j * 4);
    float2 ha = __half22float2(*(const __half2*)&hraw.x);
    float2 hb = __half22float2(*(const __half2*)&hraw.y);
    float2 r0 = ((const float2*)(tabh + (size_t)i * 64))[j];
    float2 r1 = ((const float2*)(tabh + (size_t)i * 64 + 64))[j];
    float2 t0a = __half22float2(*(const __half2*)&r0.x);
    float2 t0b = __half22float2(*(const __half2*)&r0.y);
    float2 t1a = __half22float2(*(const __half2*)&r1.x);
    float2 t1b = __half22float2(*(const __half2*)&r1.y);
    float4 m;
    m.x = ha.x * (a.x * t0a.x + a.y * t1a.x);
    m.y = ha.y * (a.x * t0a.y + a.y * t1a.y);
    m.z = hb.x * (a.x * t0b.x + a.y * t1b.x);
    m.w = hb.y * (a.x * t0b.y + a.y * t1b.y);
    red_add4(&g_agg[dd * 64 + j * 4], m);
}

// ---------------- pooling ----------------
__global__ void k_pool(const int* __restrict__ batch) {
    int gid = blockIdx.x * 256 + threadIdx.x;
    if (gid >= N_ATOMS * 16) return;
    int n = gid >> 4, j = gid & 15;
    int b = batch[n];
    float4 v = ((const float4*)g_h)[n * 16 + j];
    red_add4(&g_pool[b * 64 + j * 4], v);
    if (j == 0) red_add1(&g_pool[B_GRAPHS * 64 + b], 1.0f);
}

// ---------------- final MLP ----------------
__global__ void k_final(const float* __restrict__ fc1w, const float* __restrict__ fc1b,
                        const float* __restrict__ fc2w, const float* __restrict__ fc2b,
                        float* __restrict__ out) {
    int g = blockIdx.x;
    int j = threadIdx.x;
    float cnt = fmaxf(g_pool[B_GRAPHS * 64 + g], 1.0f);
    float inv = 1.0f / cnt;
    float hid = fc1b[j];
    #pragma unroll
    for (int k = 0; k < 64; ++k)
        hid += (g_pool[g * 64 + k] * inv) * fc1w[k * 32 + j];
    hid = fmaxf(hid, 0.0f);
    float p = hid * fc2w[j];
    #pragma unroll
    for (int o = 16; o > 0; o >>= 1) p += __shfl_down_sync(0xffffffffu, p, o);
    if (j == 0) out[g] = p + fc2b[0];
}

// ---------------- launch ----------------
extern "C" void kernel_launch(void* const* d_in, const int* in_sizes, int n_in,
                              void* d_out, int out_size) {
    const int*   z     = (const int*)d_in[0];
    const float* pos   = (const float*)d_in[1];
    const int*   batch = (const int*)d_in[2];
    const int*   ei    = (const int*)d_in[3];
    const float* embed = (const float*)d_in[4];
    const float* w1    = (const float*)d_in[5];
    const float* b1    = (const float*)d_in[6];
    const float* w2    = (const float*)d_in[7];
    const float* b2    = (const float*)d_in[8];
    const float* linw  = (const float*)d_in[9];
    const float* loutw = (const float*)d_in[10];
    const float* loutb = (const float*)d_in[11];
    const float* fc1w  = (const float*)d_in[12];
    const float* fc1b  = (const float*)d_in[13];
    const float* fc2w  = (const float*)d_in[14];
    const float* fc2b  = (const float*)d_in[15];
    float* out = (float*)d_out;

    const int GB = (N_ATOMS + 127) / 128;   // 391 blocks x 128 threads

    k_embed<<<(N_ATOMS * 16 + 255) / 256, 256>>>(z, embed);
    k_edge <<<(N_EDGES + 255) / 256, 256>>>(ei, pos);
    k_table<<<L_LAYERS * (T_TAB / 64), 64>>>(w1, b1, w2, b2);

    k_hj0<<<GB, 128>>>(linw);   // hj for layer 0, agg zeroed

    for (int l = 0; l < L_LAYERS; ++l) {
        k_msg<<<(N_EDGES * 16 + 255) / 256, 256>>>(ei, l);
        int do2 = (l < L_LAYERS - 1);
        k_fused<<<GB, 128>>>(loutw + (size_t)l * 64 * 64,
                             loutb + (size_t)l * 64,
                             do2 ? (linw + (size_t)(l + 1) * 64 * 64) : linw,
                             do2);
    }

    k_pool <<<(N_ATOMS * 16 + 255) / 256, 256>>>(batch);
    k_final<<<B_GRAPHS, 32>>>(fc1w, fc1b, fc2w, fc2b, out);
}